// round 1
// baseline (speedup 1.0000x reference)
#include <cuda_runtime.h>
#include <math.h>

#define N_   8
#define CI1  32
#define CO   64
#define T_   8
#define H_   256
#define W_   256
#define HW   (H_*W_)
#define BN_EPS 1e-5f

// ---------------- device scratch (static, no allocation) ----------------
__device__ float d_y1[(size_t)N_ * CO * HW];          // raw layer-1 conv output (134 MB)
__device__ float d_gates[2][N_][5][CO];               // softmax gates per layer
__device__ float d_wk1[N_ * CO * CI1 * 25];           // per-sample mixed kernels, layer 1
__device__ float d_wk2[N_ * CO * CO  * 25];           // per-sample mixed kernels, layer 2
__device__ float d_psum[CO * N_];                     // BN partial sums
__device__ float d_psq [CO * N_];                     // BN partial sums of squares
__device__ float d_bn[2][2][CO];                      // [layer][0=scale,1=bias][c]

// ---------------- gates: softmax(t @ gw^T + gb) over 5 experts ----------------
__global__ void gate_kernel(const float* __restrict__ t,
                            const float* __restrict__ gw1, const float* __restrict__ gb1,
                            const float* __restrict__ gw2, const float* __restrict__ gb2) {
    int l = blockIdx.x;                 // layer
    const float* gw = l ? gw2 : gw1;
    const float* gb = l ? gb2 : gb1;
    int n = threadIdx.x / CO;           // 512 threads: n in [0,8), o in [0,64)
    int o = threadIdx.x % CO;
    float tt[T_];
#pragma unroll
    for (int k = 0; k < T_; k++) tt[k] = t[n * T_ + k];
    float lg[5];
    float m = -1e30f;
#pragma unroll
    for (int e = 0; e < 5; e++) {
        int row = e * CO + o;
        float s = gb[row];
#pragma unroll
        for (int k = 0; k < T_; k++) s = fmaf(tt[k], gw[row * T_ + k], s);
        lg[e] = s;
        m = fmaxf(m, s);
    }
    float sum = 0.f;
#pragma unroll
    for (int e = 0; e < 5; e++) { lg[e] = expf(lg[e] - m); sum += lg[e]; }
    float inv = 1.f / sum;
#pragma unroll
    for (int e = 0; e < 5; e++) d_gates[l][n][e][o] = lg[e] * inv;
}

// ---------------- build per-sample mixed 5x5 kernels ----------------
// wk layout: [((n*CO + o)*Ci + i)*25 + tap]
__global__ void build_w(int layer, int Ci,
                        const float* __restrict__ w5, const float* __restrict__ w3,
                        const float* __restrict__ w1, const float* __restrict__ a3,
                        const float* __restrict__ a5, float* __restrict__ wk) {
    int idx = blockIdx.x * blockDim.x + threadIdx.x;
    int total = N_ * CO * Ci * 25;
    if (idx >= total) return;
    int tap  = idx % 25;
    int rest = idx / 25;
    int i = rest % Ci; rest /= Ci;
    int o = rest % CO;
    int n = rest / CO;
    int dy = tap / 5, dx = tap % 5;
    float g0 = d_gates[layer][n][0][o];
    float g1 = d_gates[layer][n][1][o];
    float g2 = d_gates[layer][n][2][o];
    float g3 = d_gates[layer][n][3][o];
    float g4 = d_gates[layer][n][4][o];
    int oi = o * Ci + i;
    float v = g0 * w5[oi * 25 + tap] + g4 * a5[oi] * (1.f / 125.f);
    if (dy >= 1 && dy <= 3 && dx >= 1 && dx <= 3) {
        v += g1 * w3[oi * 9 + (dy - 1) * 3 + (dx - 1)];
        v += g3 * a3[oi] * (1.f / 27.f);
    }
    if (dy == 2 && dx == 2) v += g2 * w1[oi];
    wk[idx] = v;
}

// ---------------- direct 5x5 SAME conv, per-sample weights ----------------
// Block: 256 threads. Output tile 32x32, each thread: 4 rows (stride 8) x 8 co.
// bnLayer >= 0: apply BN(scale,bias)+ReLU from d_bn[bnLayer] to the INPUT on load.
template <int CI>
__global__ void __launch_bounds__(256) conv5(const float* __restrict__ in,
                                             const float* __restrict__ wk,
                                             float* __restrict__ out,
                                             int bnLayer) {
    __shared__ float in_s[36 * 36];
    __shared__ float w_s[8 * 25];

    int tileX = blockIdx.x & 7;
    int tileY = blockIdx.x >> 3;
    int coB   = blockIdx.y * 8;
    int n     = blockIdx.z;
    int tid   = threadIdx.x;
    int col   = tid & 31;
    int row0  = tid >> 5;
    int gx0 = tileX * 32, gy0 = tileY * 32;

    float acc[4][8];
#pragma unroll
    for (int p = 0; p < 4; p++)
#pragma unroll
        for (int c = 0; c < 8; c++) acc[p][c] = 0.f;

    const float* inN = in + (size_t)n * CI * HW;
    const float* wkN = wk + ((size_t)(n * CO) + coB) * CI * 25;
    const bool bn = (bnLayer >= 0);

    for (int ci = 0; ci < CI; ci++) {
        float scale = 1.f, bias = 0.f;
        if (bn) { scale = d_bn[bnLayer][0][ci]; bias = d_bn[bnLayer][1][ci]; }
        const float* inC = inN + (size_t)ci * HW;
        // cooperative load of 36x36 halo tile (zero padded) with fused BN+ReLU
        for (int k = tid; k < 36 * 36; k += 256) {
            int r = k / 36, c = k % 36;
            int gy = gy0 - 2 + r, gx = gx0 - 2 + c;
            float v = 0.f;
            if (gy >= 0 && gy < H_ && gx >= 0 && gx < W_) v = inC[gy * W_ + gx];
            if (bn) v = fmaxf(fmaf(v, scale, bias), 0.f);
            in_s[k] = v;
        }
        if (tid < 200)
            w_s[tid] = wkN[(size_t)(tid / 25) * CI * 25 + ci * 25 + (tid % 25)];
        __syncthreads();

#pragma unroll
        for (int tap = 0; tap < 25; tap++) {
            int dy = tap / 5, dx = tap % 5;
            float wv[8];
#pragma unroll
            for (int c = 0; c < 8; c++) wv[c] = w_s[c * 25 + tap];  // broadcast
#pragma unroll
            for (int p = 0; p < 4; p++) {
                float iv = in_s[(row0 + p * 8 + dy) * 36 + col + dx];
#pragma unroll
                for (int c = 0; c < 8; c++) acc[p][c] = fmaf(iv, wv[c], acc[p][c]);
            }
        }
        __syncthreads();
    }

#pragma unroll
    for (int c = 0; c < 8; c++) {
        float* o = out + (size_t)(n * CO + coB + c) * HW;
#pragma unroll
        for (int p = 0; p < 4; p++)
            o[(gy0 + row0 + p * 8) * W_ + gx0 + col] = acc[p][c];
    }
}

// ---------------- BN stats: per-(c,n) block partial sum / sumsq ----------------
__global__ void stats_kernel(const float* __restrict__ y) {
    int c = blockIdx.x;  // channel
    int n = blockIdx.y;  // sample
    const float4* p = (const float4*)(y + (size_t)(n * CO + c) * HW);
    float s = 0.f, sq = 0.f;
    for (int k = threadIdx.x; k < HW / 4; k += 256) {
        float4 v = p[k];
        s  += v.x + v.y + v.z + v.w;
        sq += v.x * v.x + v.y * v.y + v.z * v.z + v.w * v.w;
    }
    __shared__ float ss[256], sqq[256];
    ss[threadIdx.x] = s; sqq[threadIdx.x] = sq;
    __syncthreads();
    for (int st = 128; st > 0; st >>= 1) {
        if (threadIdx.x < st) {
            ss[threadIdx.x]  += ss[threadIdx.x + st];
            sqq[threadIdx.x] += sqq[threadIdx.x + st];
        }
        __syncthreads();
    }
    if (threadIdx.x == 0) {
        d_psum[c * N_ + n] = ss[0];
        d_psq [c * N_ + n] = sqq[0];
    }
}

__global__ void finalize_kernel(int layer, const float* __restrict__ gamma,
                                const float* __restrict__ beta) {
    int c = threadIdx.x;  // 64 threads
    float s = 0.f, sq = 0.f;
#pragma unroll
    for (int n = 0; n < N_; n++) { s += d_psum[c * N_ + n]; sq += d_psq[c * N_ + n]; }
    const float cnt = (float)(N_ * HW);
    float mean = s / cnt;
    float var  = sq / cnt - mean * mean;
    float rs   = rsqrtf(var + BN_EPS);
    float scale = gamma[c] * rs;
    d_bn[layer][0][c] = scale;
    d_bn[layer][1][c] = beta[c] - mean * scale;
}

// ---------------- final BN+ReLU in-place on output ----------------
__global__ void bn_apply(float* __restrict__ y) {
    size_t i = (size_t)blockIdx.x * blockDim.x + threadIdx.x;  // float4 index
    int c = (int)((i / (HW / 4)) % CO);
    float4* p = (float4*)y;
    float4 v = p[i];
    float scale = d_bn[1][0][c], bias = d_bn[1][1][c];
    v.x = fmaxf(fmaf(v.x, scale, bias), 0.f);
    v.y = fmaxf(fmaf(v.y, scale, bias), 0.f);
    v.z = fmaxf(fmaf(v.z, scale, bias), 0.f);
    v.w = fmaxf(fmaf(v.w, scale, bias), 0.f);
    p[i] = v;
}

// ---------------- launch ----------------
extern "C" void kernel_launch(void* const* d_in, const int* in_sizes, int n_in,
                              void* d_out, int out_size) {
    const float* x      = (const float*)d_in[0];
    const float* t      = (const float*)d_in[1];
    const float* w5_1   = (const float*)d_in[2];
    const float* w3_1   = (const float*)d_in[3];
    const float* w1_1   = (const float*)d_in[4];
    const float* a3_1   = (const float*)d_in[5];
    const float* a5_1   = (const float*)d_in[6];
    const float* gw_1   = (const float*)d_in[7];
    const float* gb_1   = (const float*)d_in[8];
    const float* gamma_1= (const float*)d_in[9];
    const float* beta_1 = (const float*)d_in[10];
    const float* w5_2   = (const float*)d_in[11];
    const float* w3_2   = (const float*)d_in[12];
    const float* w1_2   = (const float*)d_in[13];
    const float* a3_2   = (const float*)d_in[14];
    const float* a5_2   = (const float*)d_in[15];
    const float* gw_2   = (const float*)d_in[16];
    const float* gb_2   = (const float*)d_in[17];
    const float* gamma_2= (const float*)d_in[18];
    const float* beta_2 = (const float*)d_in[19];
    float* out = (float*)d_out;

    float *y1, *wk1, *wk2;
    cudaGetSymbolAddress((void**)&y1,  d_y1);
    cudaGetSymbolAddress((void**)&wk1, d_wk1);
    cudaGetSymbolAddress((void**)&wk2, d_wk2);

    // 1. gates for both layers
    gate_kernel<<<2, 512>>>(t, gw_1, gb_1, gw_2, gb_2);

    // 2. per-sample mixed kernels
    build_w<<<(N_ * CO * CI1 * 25 + 255) / 256, 256>>>(0, CI1, w5_1, w3_1, w1_1, a3_1, a5_1, wk1);
    build_w<<<(N_ * CO * CO  * 25 + 255) / 256, 256>>>(1, CO,  w5_2, w3_2, w1_2, a3_2, a5_2, wk2);

    // 3. layer 1: conv (raw) -> stats -> bn params
    dim3 gconv(64, CO / 8, N_);
    conv5<CI1><<<gconv, 256>>>(x, wk1, y1, -1);
    stats_kernel<<<dim3(CO, N_), 256>>>(y1);
    finalize_kernel<<<1, 64>>>(0, gamma_1, beta_1);

    // 4. layer 2: conv (BN1+ReLU fused into input load) -> stats -> bn params -> apply
    conv5<CO><<<gconv, 256>>>(y1, wk2, out, 0);
    stats_kernel<<<dim3(CO, N_), 256>>>(out);
    finalize_kernel<<<1, 64>>>(1, gamma_2, beta_2);
    bn_apply<<<(N_ * CO * HW / 4) / 256, 256>>>(out);
}

// round 2
// speedup vs baseline: 1.4616x; 1.4616x over previous
#include <cuda_runtime.h>
#include <math.h>

#define N_   8
#define CI1  32
#define CO   64
#define T_   8
#define H_   256
#define W_   256
#define HW   (H_*W_)
#define BN_EPS 1e-5f

// ---------------- device scratch (static, no allocation) ----------------
__device__ float d_y1[(size_t)N_ * CO * HW];          // raw layer-1 conv output (134 MB)
__device__ float d_gates[2][N_][5][CO];               // softmax gates per layer
__device__ float d_wk1[N_ * CI1 * 25 * CO];           // per-sample mixed kernels [n][ci][tap][co]
__device__ float d_wk2[N_ * CO  * 25 * CO];
__device__ float d_psum[CO * N_];                     // BN partial sums
__device__ float d_psq [CO * N_];                     // BN partial sums of squares
__device__ float d_bn[2][2][CO];                      // [layer][0=scale,1=bias][c]

// ---------------- packed f32x2 helpers (Blackwell FFMA2) ----------------
__device__ __forceinline__ unsigned long long pk2(float lo, float hi) {
    unsigned long long r;
    asm("mov.b64 %0, {%1, %2};" : "=l"(r)
        : "r"(__float_as_uint(lo)), "r"(__float_as_uint(hi)));
    return r;
}
__device__ __forceinline__ void fma2(unsigned long long& d,
                                     unsigned long long a, unsigned long long b) {
    asm("fma.rn.f32x2 %0, %1, %2, %0;" : "+l"(d) : "l"(a), "l"(b));
}
__device__ __forceinline__ float2 upk2(unsigned long long v) {
    unsigned int lo, hi;
    asm("mov.b64 {%0, %1}, %2;" : "=r"(lo), "=r"(hi) : "l"(v));
    return make_float2(__uint_as_float(lo), __uint_as_float(hi));
}

// ---------------- gates: softmax(t @ gw^T + gb) over 5 experts ----------------
__global__ void gate_kernel(const float* __restrict__ t,
                            const float* __restrict__ gw1, const float* __restrict__ gb1,
                            const float* __restrict__ gw2, const float* __restrict__ gb2) {
    int l = blockIdx.x;
    const float* gw = l ? gw2 : gw1;
    const float* gb = l ? gb2 : gb1;
    int n = threadIdx.x / CO;
    int o = threadIdx.x % CO;
    float tt[T_];
#pragma unroll
    for (int k = 0; k < T_; k++) tt[k] = t[n * T_ + k];
    float lg[5];
    float m = -1e30f;
#pragma unroll
    for (int e = 0; e < 5; e++) {
        int row = e * CO + o;
        float s = gb[row];
#pragma unroll
        for (int k = 0; k < T_; k++) s = fmaf(tt[k], gw[row * T_ + k], s);
        lg[e] = s;
        m = fmaxf(m, s);
    }
    float sum = 0.f;
#pragma unroll
    for (int e = 0; e < 5; e++) { lg[e] = expf(lg[e] - m); sum += lg[e]; }
    float inv = 1.f / sum;
#pragma unroll
    for (int e = 0; e < 5; e++) d_gates[l][n][e][o] = lg[e] * inv;
}

// ---------------- build per-sample mixed 5x5 kernels ----------------
// OUT layout: [n][ci][tap][co]  ->  (((n*Ci + i)*25 + tap)*CO + o)
__global__ void build_w(int layer, int Ci,
                        const float* __restrict__ w5, const float* __restrict__ w3,
                        const float* __restrict__ w1, const float* __restrict__ a3,
                        const float* __restrict__ a5, float* __restrict__ wk) {
    int idx = blockIdx.x * blockDim.x + threadIdx.x;
    int total = N_ * CO * Ci * 25;
    if (idx >= total) return;
    int tap  = idx % 25;
    int rest = idx / 25;
    int i = rest % Ci; rest /= Ci;
    int o = rest % CO;
    int n = rest / CO;
    int dy = tap / 5, dx = tap % 5;
    float g0 = d_gates[layer][n][0][o];
    float g1 = d_gates[layer][n][1][o];
    float g2 = d_gates[layer][n][2][o];
    float g3 = d_gates[layer][n][3][o];
    float g4 = d_gates[layer][n][4][o];
    int oi = o * Ci + i;
    float v = g0 * w5[oi * 25 + tap] + g4 * a5[oi] * (1.f / 125.f);
    if (dy >= 1 && dy <= 3 && dx >= 1 && dx <= 3) {
        v += g1 * w3[oi * 9 + (dy - 1) * 3 + (dx - 1)];
        v += g3 * a3[oi] * (1.f / 27.f);
    }
    if (dy == 2 && dx == 2) v += g2 * w1[oi];
    wk[(((size_t)(n * Ci + i) * 25 + tap) * CO + o)] = v;
}

// ---------------- direct 5x5 SAME conv, per-sample weights ----------------
// 256 threads, 32x32 output tile, 8 co per block (packed as 4 f32x2 pairs),
// 4 output rows per thread. All weights for the block preloaded to smem once.
// Input tile double-buffered, one __syncthreads per ci.
template <int CI>
__global__ void __launch_bounds__(256) conv5(const float* __restrict__ in,
                                             const float* __restrict__ wk,
                                             float* __restrict__ out,
                                             int bnLayer) {
    extern __shared__ float smem[];
    float* w_s  = smem;                 // [CI][25][8]
    float* tile = smem + CI * 200;      // [2][36*36]

    int tileX = blockIdx.x & 7;
    int tileY = blockIdx.x >> 3;
    int coB   = blockIdx.y * 8;
    int n     = blockIdx.z;
    int tid   = threadIdx.x;
    int col   = tid & 31;
    int row0  = tid >> 5;
    int gx0 = tileX * 32, gy0 = tileY * 32;
    const bool bn = (bnLayer >= 0);

    // ---- preload ALL weights for this (n, coB) block: [ci][tap][8] ----
    {
        const float* wkN = wk + (size_t)n * CI * 25 * CO + coB;
        for (int k = tid; k < CI * 200; k += 256) {
            int c = k & 7, g = k >> 3;           // g = ci*25+tap
            w_s[k] = wkN[(size_t)g * CO + c];
        }
    }

    const float* inN = in + (size_t)n * CI * HW;

    // ---- tile loader (zero-padded halo, optional fused BN+ReLU on input) ----
    auto loadTile = [&](float* dst, int ci) {
        float scale = 1.f, bias = 0.f;
        if (bn) { scale = d_bn[bnLayer][0][ci]; bias = d_bn[bnLayer][1][ci]; }
        const float* inC = inN + (size_t)ci * HW;
        for (int k = tid; k < 36 * 36; k += 256) {
            int r = k / 36, c = k % 36;
            int gy = gy0 - 2 + r, gx = gx0 - 2 + c;
            float v = 0.f;
            if ((unsigned)gy < H_ && (unsigned)gx < W_) v = inC[gy * W_ + gx];
            if (bn) v = fmaxf(fmaf(v, scale, bias), 0.f);
            dst[k] = v;
        }
    };

    unsigned long long acc[4][4];
#pragma unroll
    for (int p = 0; p < 4; p++)
#pragma unroll
        for (int c = 0; c < 4; c++) acc[p][c] = 0ull;

    loadTile(tile, 0);
    __syncthreads();

    for (int ci = 0; ci < CI; ci++) {
        int cur = ci & 1;
        if (ci + 1 < CI) loadTile(tile + (1 - cur) * 1296, ci + 1);

        const float* in_c = tile + cur * 1296;
        const float* wrow = w_s + ci * 200;

#pragma unroll
        for (int tap = 0; tap < 25; tap++) {
            const int dy = tap / 5, dx = tap % 5;
            float4 wa = *reinterpret_cast<const float4*>(wrow + tap * 8);
            float4 wb = *reinterpret_cast<const float4*>(wrow + tap * 8 + 4);
            unsigned long long W0 = pk2(wa.x, wa.y);
            unsigned long long W1 = pk2(wa.z, wa.w);
            unsigned long long W2 = pk2(wb.x, wb.y);
            unsigned long long W3 = pk2(wb.z, wb.w);
#pragma unroll
            for (int p = 0; p < 4; p++) {
                float iv = in_c[(row0 + p * 8 + dy) * 36 + col + dx];
                unsigned long long IV = pk2(iv, iv);
                fma2(acc[p][0], IV, W0);
                fma2(acc[p][1], IV, W1);
                fma2(acc[p][2], IV, W2);
                fma2(acc[p][3], IV, W3);
            }
        }
        __syncthreads();
    }

    // ---- store ----
#pragma unroll
    for (int c2 = 0; c2 < 4; c2++) {
        float* o0 = out + (size_t)(n * CO + coB + 2 * c2)     * HW;
        float* o1 = out + (size_t)(n * CO + coB + 2 * c2 + 1) * HW;
#pragma unroll
        for (int p = 0; p < 4; p++) {
            float2 v = upk2(acc[p][c2]);
            int off = (gy0 + row0 + p * 8) * W_ + gx0 + col;
            o0[off] = v.x;
            o1[off] = v.y;
        }
    }
}

// ---------------- BN stats: per-(c,n) block partial sum / sumsq ----------------
__global__ void stats_kernel(const float* __restrict__ y) {
    int c = blockIdx.x;
    int n = blockIdx.y;
    const float4* p = (const float4*)(y + (size_t)(n * CO + c) * HW);
    float s = 0.f, sq = 0.f;
    for (int k = threadIdx.x; k < HW / 4; k += 256) {
        float4 v = p[k];
        s  += v.x + v.y + v.z + v.w;
        sq += v.x * v.x + v.y * v.y + v.z * v.z + v.w * v.w;
    }
    __shared__ float ss[256], sqq[256];
    ss[threadIdx.x] = s; sqq[threadIdx.x] = sq;
    __syncthreads();
    for (int st = 128; st > 0; st >>= 1) {
        if (threadIdx.x < st) {
            ss[threadIdx.x]  += ss[threadIdx.x + st];
            sqq[threadIdx.x] += sqq[threadIdx.x + st];
        }
        __syncthreads();
    }
    if (threadIdx.x == 0) {
        d_psum[c * N_ + n] = ss[0];
        d_psq [c * N_ + n] = sqq[0];
    }
}

__global__ void finalize_kernel(int layer, const float* __restrict__ gamma,
                                const float* __restrict__ beta) {
    int c = threadIdx.x;
    float s = 0.f, sq = 0.f;
#pragma unroll
    for (int n = 0; n < N_; n++) { s += d_psum[c * N_ + n]; sq += d_psq[c * N_ + n]; }
    const float cnt = (float)(N_ * HW);
    float mean = s / cnt;
    float var  = sq / cnt - mean * mean;
    float rs   = rsqrtf(var + BN_EPS);
    float scale = gamma[c] * rs;
    d_bn[layer][0][c] = scale;
    d_bn[layer][1][c] = beta[c] - mean * scale;
}

// ---------------- final BN+ReLU in-place on output ----------------
__global__ void bn_apply(float* __restrict__ y) {
    size_t i = (size_t)blockIdx.x * blockDim.x + threadIdx.x;
    int c = (int)((i / (HW / 4)) % CO);
    float4* p = (float4*)y;
    float4 v = p[i];
    float scale = d_bn[1][0][c], bias = d_bn[1][1][c];
    v.x = fmaxf(fmaf(v.x, scale, bias), 0.f);
    v.y = fmaxf(fmaf(v.y, scale, bias), 0.f);
    v.z = fmaxf(fmaf(v.z, scale, bias), 0.f);
    v.w = fmaxf(fmaf(v.w, scale, bias), 0.f);
    p[i] = v;
}

// ---------------- launch ----------------
extern "C" void kernel_launch(void* const* d_in, const int* in_sizes, int n_in,
                              void* d_out, int out_size) {
    const float* x      = (const float*)d_in[0];
    const float* t      = (const float*)d_in[1];
    const float* w5_1   = (const float*)d_in[2];
    const float* w3_1   = (const float*)d_in[3];
    const float* w1_1   = (const float*)d_in[4];
    const float* a3_1   = (const float*)d_in[5];
    const float* a5_1   = (const float*)d_in[6];
    const float* gw_1   = (const float*)d_in[7];
    const float* gb_1   = (const float*)d_in[8];
    const float* gamma_1= (const float*)d_in[9];
    const float* beta_1 = (const float*)d_in[10];
    const float* w5_2   = (const float*)d_in[11];
    const float* w3_2   = (const float*)d_in[12];
    const float* w1_2   = (const float*)d_in[13];
    const float* a3_2   = (const float*)d_in[14];
    const float* a5_2   = (const float*)d_in[15];
    const float* gw_2   = (const float*)d_in[16];
    const float* gb_2   = (const float*)d_in[17];
    const float* gamma_2= (const float*)d_in[18];
    const float* beta_2 = (const float*)d_in[19];
    float* out = (float*)d_out;

    float *y1, *wk1, *wk2;
    cudaGetSymbolAddress((void**)&y1,  d_y1);
    cudaGetSymbolAddress((void**)&wk1, d_wk1);
    cudaGetSymbolAddress((void**)&wk2, d_wk2);

    const int smem1 = CI1 * 200 * 4 + 2 * 1296 * 4;   // 35968 B
    const int smem2 = CO  * 200 * 4 + 2 * 1296 * 4;   // 61568 B
    cudaFuncSetAttribute(conv5<CI1>, cudaFuncAttributeMaxDynamicSharedMemorySize, smem1);
    cudaFuncSetAttribute(conv5<CO>,  cudaFuncAttributeMaxDynamicSharedMemorySize, smem2);

    // 1. gates for both layers
    gate_kernel<<<2, 512>>>(t, gw_1, gb_1, gw_2, gb_2);

    // 2. per-sample mixed kernels (layout [n][ci][tap][co])
    build_w<<<(N_ * CO * CI1 * 25 + 255) / 256, 256>>>(0, CI1, w5_1, w3_1, w1_1, a3_1, a5_1, wk1);
    build_w<<<(N_ * CO * CO  * 25 + 255) / 256, 256>>>(1, CO,  w5_2, w3_2, w1_2, a3_2, a5_2, wk2);

    // 3. layer 1: conv (raw) -> stats -> bn params
    dim3 gconv(64, CO / 8, N_);
    conv5<CI1><<<gconv, 256, smem1>>>(x, wk1, y1, -1);
    stats_kernel<<<dim3(CO, N_), 256>>>(y1);
    finalize_kernel<<<1, 64>>>(0, gamma_1, beta_1);

    // 4. layer 2: conv (BN1+ReLU fused into input load) -> stats -> bn -> apply
    conv5<CO><<<gconv, 256, smem2>>>(y1, wk2, out, 0);
    stats_kernel<<<dim3(CO, N_), 256>>>(out);
    finalize_kernel<<<1, 64>>>(1, gamma_2, beta_2);
    bn_apply<<<(N_ * CO * HW / 4) / 256, 256>>>(out);
}